// round 10
// baseline (speedup 1.0000x reference)
#include <cuda_runtime.h>

// Problem constants (fixed by the dataset)
#define BATCH 8192
#define HDIM  512
#define DPTH  16
#define WPB   8                 // warps per block
#define NBLK  (BATCH / WPB)     // 1024 CTAs

// Scratch (__device__ globals per allocation rules). g_done starts 0 and is
// reset by the last CTA each launch -> clean state for every graph replay.
__device__ float g_partial[NBLK];
__device__ unsigned int g_done;

// 256-bit loads (sm_103a): ptxas requires .v8.b32 for L2 eviction-priority
// modifiers. Weights -> evict_last (protect duplicate-word reuse in L2);
// hidden -> evict_first (stream-once, don't displace weights).
__device__ __forceinline__ void ldg256_el(const float* p, float v[8]) {
    unsigned r0, r1, r2, r3, r4, r5, r6, r7;
    asm volatile("ld.global.nc.L2::evict_last.v8.b32 {%0,%1,%2,%3,%4,%5,%6,%7}, [%8];"
                 : "=r"(r0), "=r"(r1), "=r"(r2), "=r"(r3),
                   "=r"(r4), "=r"(r5), "=r"(r6), "=r"(r7)
                 : "l"(p));
    v[0] = __uint_as_float(r0); v[1] = __uint_as_float(r1);
    v[2] = __uint_as_float(r2); v[3] = __uint_as_float(r3);
    v[4] = __uint_as_float(r4); v[5] = __uint_as_float(r5);
    v[6] = __uint_as_float(r6); v[7] = __uint_as_float(r7);
}
__device__ __forceinline__ void ldg256_ef(const float* p, float v[8]) {
    unsigned r0, r1, r2, r3, r4, r5, r6, r7;
    asm volatile("ld.global.nc.L2::evict_first.v8.b32 {%0,%1,%2,%3,%4,%5,%6,%7}, [%8];"
                 : "=r"(r0), "=r"(r1), "=r"(r2), "=r"(r3),
                   "=r"(r4), "=r"(r5), "=r"(r6), "=r"(r7)
                 : "l"(p));
    v[0] = __uint_as_float(r0); v[1] = __uint_as_float(r1);
    v[2] = __uint_as_float(r2); v[3] = __uint_as_float(r3);
    v[4] = __uint_as_float(r4); v[5] = __uint_as_float(r5);
    v[6] = __uint_as_float(r6); v[7] = __uint_as_float(r7);
}

// Warp-per-sample streaming kernel + fused deterministic reduction.
// Structure identical to the 43.5us R8 kernel; loads widened to LDG.256 with
// L2 eviction hints. Lane owns float chunks [8l,8l+8) and [8l+256,8l+264)
// of every 512-float row (same columns in hidden and each weight row).
__global__ __launch_bounds__(256) void hs_fused_kernel(
    const float* __restrict__ hidden,     // [BATCH, HDIM]
    const int*   __restrict__ target,     // [BATCH]
    const float* __restrict__ weights,    // [V, DPTH, HDIM]
    const float* __restrict__ codes,      // [V, DPTH]
    const int*   __restrict__ lengths,    // [V]
    float*       __restrict__ out)        // [1]
{
    const int tid  = threadIdx.x;
    const int warp = tid >> 5;
    const int lane = tid & 31;
    const int b    = blockIdx.x * WPB + warp;

    const int word = target[b];           // broadcast load

    // hidden[b]
    const float* hp = hidden + (size_t)b * HDIM + lane * 8;
    float h0[8], h1[8];
    ldg256_ef(hp, h0);
    ldg256_ef(hp + 256, h1);

    const float* wp = weights + (size_t)word * DPTH * HDIM + lane * 8;

    float acc[DPTH];
    #pragma unroll
    for (int d = 0; d < DPTH; d += 2) {
        float a0[8], a1[8], c0[8], c1[8];
        const float* rp = wp + (size_t)d * HDIM;
        ldg256_el(rp, a0);
        ldg256_el(rp + 256, a1);
        ldg256_el(rp + HDIM, c0);
        ldg256_el(rp + HDIM + 256, c1);
        float s0 = 0.0f, s1 = 0.0f;
        #pragma unroll
        for (int j = 0; j < 8; j++) {
            s0 += a0[j] * h0[j] + a1[j] * h1[j];
            s1 += c0[j] * h0[j] + c1[j] * h1[j];
        }
        acc[d]     = s0;
        acc[d + 1] = s1;
    }

    // ---- Transposed cross-lane reduction: lane l ends with logit d = l & 15
    #pragma unroll
    for (int i = 0; i < 16; i++)
        acc[i] += __shfl_xor_sync(0xffffffff, acc[i], 16);
    #pragma unroll
    for (int i = 0; i < 8; i++) {
        const bool hi = (lane & 8);
        float send = hi ? acc[i] : acc[i + 8];
        float o = __shfl_xor_sync(0xffffffff, send, 8);
        acc[i] = (hi ? acc[i + 8] : acc[i]) + o;
    }
    #pragma unroll
    for (int i = 0; i < 4; i++) {
        const bool hi = (lane & 4);
        float send = hi ? acc[i] : acc[i + 4];
        float o = __shfl_xor_sync(0xffffffff, send, 4);
        acc[i] = (hi ? acc[i + 4] : acc[i]) + o;
    }
    #pragma unroll
    for (int i = 0; i < 2; i++) {
        const bool hi = (lane & 2);
        float send = hi ? acc[i] : acc[i + 2];
        float o = __shfl_xor_sync(0xffffffff, send, 2);
        acc[i] = (hi ? acc[i + 2] : acc[i]) + o;
    }
    {
        const bool hi = (lane & 1);
        float send = hi ? acc[0] : acc[1];
        float o = __shfl_xor_sync(0xffffffff, send, 1);
        acc[0] = (hi ? acc[1] : acc[0]) + o;
    }

    // ---- BCE-with-logits: lane l handles path node d = l & 15 ----
    const int   d = lane & 15;
    const float x = acc[0];
    const float t = codes[(size_t)word * DPTH + d];   // 64B line, bcast halves
    const int   L = lengths[word];
    float bce = fmaxf(x, 0.0f) - x * t + log1pf(expf(-fabsf(x)));
    float v   = (d < L) ? bce : 0.0f;
    #pragma unroll
    for (int o = 8; o; o >>= 1)       // sum within each 16-lane half
        v += __shfl_xor_sync(0xffffffff, v, o);

    // ---- Fused reduction ----
    __shared__ float sloss[WPB];
    __shared__ float sred[WPB];
    __shared__ bool  is_last;
    if (lane == 0) sloss[warp] = v / (float)L;
    __syncthreads();

    if (warp == 0) {
        float p = (lane < WPB) ? sloss[lane] : 0.0f;
        #pragma unroll
        for (int o = 4; o; o >>= 1)   // fixed-order tree over 8 values
            p += __shfl_xor_sync(0xffffffff, p, o);
        if (lane == 0) {
            // L2 store + release atomic from the SAME thread: orders the
            // store without any L1-flushing fence.
            asm volatile("st.global.cg.f32 [%0], %1;"
                         :: "l"(&g_partial[blockIdx.x]), "f"(p) : "memory");
            unsigned int tk;
            asm volatile("atom.release.gpu.global.add.u32 %0, [%1], %2;"
                         : "=r"(tk) : "l"(&g_done), "r"(1u) : "memory");
            is_last = (tk == NBLK - 1);
        }
    }
    __syncthreads();
    if (!is_last) return;

    // Last CTA: all other partials are release-ordered into L2 before our
    // ticket read. Fixed-order reduction -> bitwise-deterministic mean.
    if (tid == 0) g_done = 0;         // reset for next graph replay

    float acc2 = 0.0f;
    #pragma unroll
    for (int i = 0; i < NBLK / 256; i++)      // 4 values per thread
        acc2 += __ldcg(&g_partial[tid + 256 * i]);
    #pragma unroll
    for (int o = 16; o; o >>= 1)
        acc2 += __shfl_xor_sync(0xffffffff, acc2, o);
    if (lane == 0) sred[warp] = acc2;
    __syncthreads();
    if (warp == 0) {
        float s = (lane < WPB) ? sred[lane] : 0.0f;
        #pragma unroll
        for (int o = 4; o; o >>= 1)
            s += __shfl_xor_sync(0xffffffff, s, o);
        if (lane == 0) out[0] = s / (float)BATCH;
    }
}

extern "C" void kernel_launch(void* const* d_in, const int* in_sizes, int n_in,
                              void* d_out, int out_size)
{
    const float* hidden  = (const float*)d_in[0];
    const int*   target  = (const int*)  d_in[1];
    const float* weights = (const float*)d_in[2];
    const float* codes   = (const float*)d_in[3];
    const int*   lengths = (const int*)  d_in[4];
    float* out = (float*)d_out;

    hs_fused_kernel<<<NBLK, 256>>>(hidden, target, weights, codes, lengths, out);
}

// round 11
// speedup vs baseline: 1.1170x; 1.1170x over previous
#include <cuda_runtime.h>

// Problem constants (fixed by the dataset)
#define BATCH 8192
#define HDIM  512
#define DPTH  16
#define WPB   8                 // warps per block
#define NBLK  (BATCH / WPB)     // 1024 CTAs

// Scratch (__device__ globals per allocation rules). g_done starts 0 and is
// reset by the last CTA each launch -> clean state for every graph replay.
__device__ float g_partial[NBLK];
__device__ unsigned int g_done;

// Warp-per-sample streaming kernel + fused deterministic reduction.
// Body identical to the proven 43.5us R8 kernel (plain LDG.128, no eviction
// hints -- R10 falsified those). Only change: min-blocks-per-SM = 5 forces
// the register allocation to <=51 so 5 CTAs (40 warps) fit per SM, covering
// the per-warp shuffle/MUFU epilogue dead time with more resident loaders.
__global__ __launch_bounds__(256, 5) void hs_fused_kernel(
    const float* __restrict__ hidden,     // [BATCH, HDIM]
    const int*   __restrict__ target,     // [BATCH]
    const float* __restrict__ weights,    // [V, DPTH, HDIM]
    const float* __restrict__ codes,      // [V, DPTH]
    const int*   __restrict__ lengths,    // [V]
    float*       __restrict__ out)        // [1]
{
    const int tid  = threadIdx.x;
    const int warp = tid >> 5;
    const int lane = tid & 31;
    const int b    = blockIdx.x * WPB + warp;

    const int word = target[b];           // broadcast load

    // hidden[b]: lane takes float4 {lane, lane+32, lane+64, lane+96}
    const float4* hp = reinterpret_cast<const float4*>(hidden + (size_t)b * HDIM);
    float4 h[4];
    #pragma unroll
    for (int i = 0; i < 4; i++) h[i] = hp[lane + 32 * i];

    const float4* wp =
        reinterpret_cast<const float4*>(weights + (size_t)word * DPTH * HDIM);

    float acc[DPTH];
    #pragma unroll
    for (int d = 0; d < DPTH; d += 2) {
        float4 a[4], c[4];
        #pragma unroll
        for (int i = 0; i < 4; i++) a[i] = wp[(size_t)d * 128 + lane + 32 * i];
        #pragma unroll
        for (int i = 0; i < 4; i++) c[i] = wp[(size_t)(d + 1) * 128 + lane + 32 * i];
        float s0 = 0.0f, s1 = 0.0f;
        #pragma unroll
        for (int i = 0; i < 4; i++) {
            s0 += a[i].x * h[i].x + a[i].y * h[i].y + a[i].z * h[i].z + a[i].w * h[i].w;
            s1 += c[i].x * h[i].x + c[i].y * h[i].y + c[i].z * h[i].z + c[i].w * h[i].w;
        }
        acc[d]     = s0;
        acc[d + 1] = s1;
    }

    // ---- Transposed cross-lane reduction: lane l ends with logit d = l & 15
    #pragma unroll
    for (int i = 0; i < 16; i++)
        acc[i] += __shfl_xor_sync(0xffffffff, acc[i], 16);
    #pragma unroll
    for (int i = 0; i < 8; i++) {
        const bool hi = (lane & 8);
        float send = hi ? acc[i] : acc[i + 8];
        float o = __shfl_xor_sync(0xffffffff, send, 8);
        acc[i] = (hi ? acc[i + 8] : acc[i]) + o;
    }
    #pragma unroll
    for (int i = 0; i < 4; i++) {
        const bool hi = (lane & 4);
        float send = hi ? acc[i] : acc[i + 4];
        float o = __shfl_xor_sync(0xffffffff, send, 4);
        acc[i] = (hi ? acc[i + 4] : acc[i]) + o;
    }
    #pragma unroll
    for (int i = 0; i < 2; i++) {
        const bool hi = (lane & 2);
        float send = hi ? acc[i] : acc[i + 2];
        float o = __shfl_xor_sync(0xffffffff, send, 2);
        acc[i] = (hi ? acc[i + 2] : acc[i]) + o;
    }
    {
        const bool hi = (lane & 1);
        float send = hi ? acc[0] : acc[1];
        float o = __shfl_xor_sync(0xffffffff, send, 1);
        acc[0] = (hi ? acc[1] : acc[0]) + o;
    }

    // ---- BCE-with-logits: lane l handles path node d = l & 15 ----
    const int   d = lane & 15;
    const float x = acc[0];
    const float t = codes[(size_t)word * DPTH + d];   // 64B line, bcast halves
    const int   L = lengths[word];
    float bce = fmaxf(x, 0.0f) - x * t + log1pf(expf(-fabsf(x)));
    float v   = (d < L) ? bce : 0.0f;
    #pragma unroll
    for (int o = 8; o; o >>= 1)       // sum within each 16-lane half
        v += __shfl_xor_sync(0xffffffff, v, o);

    // ---- Fused reduction ----
    __shared__ float sloss[WPB];
    __shared__ float sred[WPB];
    __shared__ bool  is_last;
    if (lane == 0) sloss[warp] = v / (float)L;
    __syncthreads();

    if (warp == 0) {
        float p = (lane < WPB) ? sloss[lane] : 0.0f;
        #pragma unroll
        for (int o = 4; o; o >>= 1)   // fixed-order tree over 8 values
            p += __shfl_xor_sync(0xffffffff, p, o);
        if (lane == 0) {
            // L2 store + release atomic from the SAME thread: orders the
            // store without any L1-flushing fence.
            asm volatile("st.global.cg.f32 [%0], %1;"
                         :: "l"(&g_partial[blockIdx.x]), "f"(p) : "memory");
            unsigned int tk;
            asm volatile("atom.release.gpu.global.add.u32 %0, [%1], %2;"
                         : "=r"(tk) : "l"(&g_done), "r"(1u) : "memory");
            is_last = (tk == NBLK - 1);
        }
    }
    __syncthreads();
    if (!is_last) return;

    // Last CTA: all other partials are release-ordered into L2 before our
    // ticket read. Fixed-order reduction -> bitwise-deterministic mean.
    if (tid == 0) g_done = 0;         // reset for next graph replay

    float acc2 = 0.0f;
    #pragma unroll
    for (int i = 0; i < NBLK / 256; i++)      // 4 values per thread
        acc2 += __ldcg(&g_partial[tid + 256 * i]);
    #pragma unroll
    for (int o = 16; o; o >>= 1)
        acc2 += __shfl_xor_sync(0xffffffff, acc2, o);
    if (lane == 0) sred[warp] = acc2;
    __syncthreads();
    if (warp == 0) {
        float s = (lane < WPB) ? sred[lane] : 0.0f;
        #pragma unroll
        for (int o = 4; o; o >>= 1)
            s += __shfl_xor_sync(0xffffffff, s, o);
        if (lane == 0) out[0] = s / (float)BATCH;
    }
}

extern "C" void kernel_launch(void* const* d_in, const int* in_sizes, int n_in,
                              void* d_out, int out_size)
{
    const float* hidden  = (const float*)d_in[0];
    const int*   target  = (const int*)  d_in[1];
    const float* weights = (const float*)d_in[2];
    const float* codes   = (const float*)d_in[3];
    const int*   lengths = (const int*)  d_in[4];
    float* out = (float*)d_out;

    hs_fused_kernel<<<NBLK, 256>>>(hidden, target, weights, codes, lengths, out);
}

// round 14
// speedup vs baseline: 1.1502x; 1.0297x over previous
#include <cuda_runtime.h>

// Problem constants (fixed by the dataset)
#define BATCH 8192
#define HDIM  512
#define DPTH  16
#define WPB   8                 // warps per block
#define NBLK  (BATCH / WPB)     // 1024 CTAs

// Per-sample losses (scratch; __device__ global per allocation rules)
__device__ float g_perword[BATCH];

// ---------------------------------------------------------------------------
// Main kernel: EXACT R6 body (fastest measured: 39.3us). Warp-per-sample,
// no smem, no __syncthreads. Ends with the PDL trigger so the reduce
// kernel's startup overlaps this grid's tail wave.
// ---------------------------------------------------------------------------
__global__ __launch_bounds__(256) void hs_main_kernel(
    const float* __restrict__ hidden,     // [BATCH, HDIM]
    const int*   __restrict__ target,     // [BATCH]
    const float* __restrict__ weights,    // [V, DPTH, HDIM]
    const float* __restrict__ codes,      // [V, DPTH]
    const int*   __restrict__ lengths)    // [V]
{
    const int warp = threadIdx.x >> 5;
    const int lane = threadIdx.x & 31;
    const int b    = blockIdx.x * WPB + warp;

    const int word = target[b];           // broadcast load

    // hidden[b]: lane takes float4 {lane, lane+32, lane+64, lane+96}
    const float4* hp = reinterpret_cast<const float4*>(hidden + (size_t)b * HDIM);
    float4 h[4];
    #pragma unroll
    for (int i = 0; i < 4; i++) h[i] = hp[lane + 32 * i];

    const float4* wp =
        reinterpret_cast<const float4*>(weights + (size_t)word * DPTH * HDIM);

    float acc[DPTH];
    #pragma unroll
    for (int d = 0; d < DPTH; d += 2) {
        float4 a[4], c[4];
        #pragma unroll
        for (int i = 0; i < 4; i++) a[i] = wp[(size_t)d * 128 + lane + 32 * i];
        #pragma unroll
        for (int i = 0; i < 4; i++) c[i] = wp[(size_t)(d + 1) * 128 + lane + 32 * i];
        float s0 = 0.0f, s1 = 0.0f;
        #pragma unroll
        for (int i = 0; i < 4; i++) {
            s0 += a[i].x * h[i].x + a[i].y * h[i].y + a[i].z * h[i].z + a[i].w * h[i].w;
            s1 += c[i].x * h[i].x + c[i].y * h[i].y + c[i].z * h[i].z + c[i].w * h[i].w;
        }
        acc[d]     = s0;
        acc[d + 1] = s1;
    }

    // ---- Transposed cross-lane reduction: lane l ends with logit d = l & 15
    #pragma unroll
    for (int i = 0; i < 16; i++)
        acc[i] += __shfl_xor_sync(0xffffffff, acc[i], 16);
    #pragma unroll
    for (int i = 0; i < 8; i++) {
        const bool hi = (lane & 8);
        float send = hi ? acc[i] : acc[i + 8];
        float o = __shfl_xor_sync(0xffffffff, send, 8);
        acc[i] = (hi ? acc[i + 8] : acc[i]) + o;
    }
    #pragma unroll
    for (int i = 0; i < 4; i++) {
        const bool hi = (lane & 4);
        float send = hi ? acc[i] : acc[i + 4];
        float o = __shfl_xor_sync(0xffffffff, send, 4);
        acc[i] = (hi ? acc[i + 4] : acc[i]) + o;
    }
    #pragma unroll
    for (int i = 0; i < 2; i++) {
        const bool hi = (lane & 2);
        float send = hi ? acc[i] : acc[i + 2];
        float o = __shfl_xor_sync(0xffffffff, send, 2);
        acc[i] = (hi ? acc[i + 2] : acc[i]) + o;
    }
    {
        const bool hi = (lane & 1);
        float send = hi ? acc[0] : acc[1];
        float o = __shfl_xor_sync(0xffffffff, send, 1);
        acc[0] = (hi ? acc[1] : acc[0]) + o;
    }

    // ---- BCE-with-logits: lane l handles path node d = l & 15 ----
    const int   d = lane & 15;
    const float x = acc[0];
    const float t = codes[(size_t)word * DPTH + d];   // 64B line, bcast halves
    const int   L = lengths[word];
    float bce = fmaxf(x, 0.0f) - x * t + log1pf(expf(-fabsf(x)));
    float v   = (d < L) ? bce : 0.0f;
    #pragma unroll
    for (int o = 8; o; o >>= 1)       // sum within each 16-lane half
        v += __shfl_xor_sync(0xffffffff, v, o);
    if (lane == 0)
        g_perword[b] = v / (float)L;

    // PDL: allow the dependent (reduce) kernel to begin its launch/prologue.
    // Its cudaGridDependencySynchronize() still waits for THIS grid's full
    // completion before it reads g_perword, so correctness is unchanged.
    cudaTriggerProgrammaticLaunchCompletion();
}

// ---------------------------------------------------------------------------
// Reduce kernel: deterministic single-CTA mean of the 8192 partials.
// Launched with ProgrammaticStreamSerialization so its startup overlaps the
// main grid's tail; grid-dependency sync gates the actual data reads.
// ---------------------------------------------------------------------------
__global__ __launch_bounds__(1024) void hs_reduce_kernel(float* __restrict__ out)
{
    cudaGridDependencySynchronize();   // primary grid complete + visible

    __shared__ float s[32];
    const int tid = threadIdx.x;
    const float4* p4 = reinterpret_cast<const float4*>(g_perword);
    float acc = 0.0f;
    #pragma unroll
    for (int i = 0; i < (BATCH / 4) / 1024; i++) {   // 2 float4 per thread
        float4 v4 = p4[tid + i * 1024];
        acc += v4.x + v4.y + v4.z + v4.w;
    }
    #pragma unroll
    for (int o = 16; o; o >>= 1)
        acc += __shfl_xor_sync(0xffffffff, acc, o);
    if ((tid & 31) == 0) s[tid >> 5] = acc;
    __syncthreads();
    if (tid < 32) {
        float v = s[tid];
        #pragma unroll
        for (int o = 16; o; o >>= 1)
            v += __shfl_xor_sync(0xffffffff, v, o);
        if (tid == 0) out[0] = v / (float)BATCH;
    }
}

extern "C" void kernel_launch(void* const* d_in, const int* in_sizes, int n_in,
                              void* d_out, int out_size)
{
    const float* hidden  = (const float*)d_in[0];
    const int*   target  = (const int*)  d_in[1];
    const float* weights = (const float*)d_in[2];
    const float* codes   = (const float*)d_in[3];
    const int*   lengths = (const int*)  d_in[4];
    float* out = (float*)d_out;

    hs_main_kernel<<<NBLK, 256>>>(hidden, target, weights, codes, lengths);

    // Dependent launch with PDL: prologue overlaps the main grid's tail.
    cudaLaunchConfig_t cfg = {};
    cfg.gridDim  = dim3(1, 1, 1);
    cfg.blockDim = dim3(1024, 1, 1);
    cfg.dynamicSmemBytes = 0;
    cfg.stream = 0;
    cudaLaunchAttribute attr[1];
    attr[0].id = cudaLaunchAttributeProgrammaticStreamSerialization;
    attr[0].val.programmaticStreamSerializationAllowed = 1;
    cfg.attrs = attr;
    cfg.numAttrs = 1;
    cudaLaunchKernelEx(&cfg, hs_reduce_kernel, out);
}